// round 15
// baseline (speedup 1.0000x reference)
#include <cuda_runtime.h>
#include <cuda_fp16.h>
#include <math.h>
#include <float.h>
#include <stdint.h>

#define B_ 2
#define T_ 2048
#define C_ 2048
#define H_ 16
#define D_ 128
#define F_ (3*C_)

// ---------------- scratch ----------------
__device__ __half g_q[(size_t)B_ * H_ * T_ * D_];   // fp16 (scaled by gain/sqrtD*log2e)
__device__ __half g_k[(size_t)B_ * H_ * T_ * D_];
__device__ __half g_v[(size_t)B_ * H_ * T_ * D_];
__device__ __half g_y[(size_t)B_ * T_ * C_];
__device__ __half g_xh[(size_t)B_ * T_ * C_];       // fp16 x
__device__ __half g_wq[(size_t)F_ * C_];            // fp16 Wqkv
__device__ __half g_wp[(size_t)C_ * C_];            // fp16 Wproj

// ---------------- helpers ----------------
#define MMA_F16(c, a, b)                                                      \
  asm volatile(                                                               \
      "mma.sync.aligned.m16n8k16.row.col.f32.f16.f16.f32 "                    \
      "{%0,%1,%2,%3}, {%4,%5,%6,%7}, {%8,%9}, {%0,%1,%2,%3};"                 \
      : "+f"((c)[0]), "+f"((c)[1]), "+f"((c)[2]), "+f"((c)[3])                \
      : "r"((a)[0]), "r"((a)[1]), "r"((a)[2]), "r"((a)[3]),                   \
        "r"((b)[0]), "r"((b)[1]))

#define LDSM_X4(r, addr)                                                      \
  asm volatile("ldmatrix.sync.aligned.m8n8.x4.shared.b16 {%0,%1,%2,%3}, [%4];"\
      : "=r"((r)[0]), "=r"((r)[1]), "=r"((r)[2]), "=r"((r)[3])                \
      : "r"(addr))

#define LDSM_X4_T(r, addr)                                                    \
  asm volatile("ldmatrix.sync.aligned.m8n8.x4.trans.shared.b16 {%0,%1,%2,%3}, [%4];"\
      : "=r"((r)[0]), "=r"((r)[1]), "=r"((r)[2]), "=r"((r)[3])                \
      : "r"(addr))

__device__ __forceinline__ uint32_t smem_u32(const void* p) {
    return (uint32_t)__cvta_generic_to_shared(p);
}
__device__ __forceinline__ void cp16(void* sdst, const void* gsrc) {
    uint32_t s = smem_u32(sdst);
    asm volatile("cp.async.cg.shared.global [%0], [%1], 16;" :: "r"(s), "l"(gsrc));
}
#define CP_COMMIT() asm volatile("cp.async.commit_group;" ::)
#define CP_WAIT1()  asm volatile("cp.async.wait_group 1;" ::)
#define CP_WAIT0()  asm volatile("cp.async.wait_group 0;" ::)

__device__ __forceinline__ uint32_t packh2(float x, float y) {
    __half2 h = __floats2half2_rn(x, y);
    return *(uint32_t*)&h;
}
__device__ __forceinline__ float exp2x(float x) {
    float y; asm("ex2.approx.ftz.f32 %0, %1;" : "=f"(y) : "f"(x)); return y;
}

// ---------------- fp32 -> fp16 convert (8 elems/thread) ----------------
__global__ __launch_bounds__(256) void cvt_f16_kernel(const float4* __restrict__ src,
                                                      uint4* __restrict__ dst, int n8)
{
    int i = blockIdx.x * blockDim.x + threadIdx.x;
    if (i < n8) {
        float4 a = src[2 * i];
        float4 b = src[2 * i + 1];
        __half2 h0 = __floats2half2_rn(a.x, a.y);
        __half2 h1 = __floats2half2_rn(a.z, a.w);
        __half2 h2 = __floats2half2_rn(b.x, b.y);
        __half2 h3 = __floats2half2_rn(b.z, b.w);
        uint4 o = {*(uint32_t*)&h0, *(uint32_t*)&h1, *(uint32_t*)&h2, *(uint32_t*)&h3};
        dst[i] = o;
    }
}

// ---------------- shared GEMM mainloop (CTA 128x128, 4 warps 64x64, KS=64) ---
#define HSTR 72
#define HS_SZ (128 * HSTR)
#define TSTR 132   // fp32 epilogue staging stride

// mainloop macro body producing acc[4][8][4]; defined as a function template
// via a plain device function operating on pointers.
struct GemmCtx {
    uint32_t aBase, bBase;
    __half *As, *Bs;
};

__device__ __forceinline__ void gemm_mainloop(
    const __half* __restrict__ A, const __half* __restrict__ Bm,
    __half* As, __half* Bs, int m0, int n0, int K, int tid,
    uint32_t aBase, uint32_t bBase, float acc[4][8][4])
{
#pragma unroll
    for (int mi = 0; mi < 4; mi++)
#pragma unroll
        for (int ni = 0; ni < 8; ni++)
#pragma unroll
            for (int c = 0; c < 4; c++) acc[mi][ni][c] = 0.f;

    uint32_t af[2][4][4], bq[2][4][4];
    const uint32_t stageBytes = HS_SZ * 2;

    auto load_stage = [&](int s, int k0) {
#pragma unroll
        for (int t = 0; t < 8; t++) {
            int cid = tid + t * 128;
            int row = cid >> 3;
            int ch8 = (cid & 7) * 8;
            cp16(&As[(size_t)s * HS_SZ + row * HSTR + ch8],
                 A + (size_t)(m0 + row) * K + k0 + ch8);
            cp16(&Bs[(size_t)s * HS_SZ + row * HSTR + ch8],
                 Bm + (size_t)(n0 + row) * K + k0 + ch8);
        }
    };

#define LD_FRAG(buf, sOff, ks)                                                  \
    do {                                                                        \
        _Pragma("unroll")                                                       \
        for (int mi = 0; mi < 4; mi++)                                          \
            LDSM_X4(af[buf][mi], aBase + (sOff) + (uint32_t)(mi * 16 * HSTR * 2) + (ks) * 32); \
        _Pragma("unroll")                                                       \
        for (int p = 0; p < 4; p++)                                             \
            LDSM_X4(bq[buf][p], bBase + (sOff) + (uint32_t)(p * 16 * HSTR * 2) + (ks) * 32);   \
    } while (0)

#define DO_MMA(buf)                                                             \
    do {                                                                        \
        _Pragma("unroll")                                                       \
        for (int mi = 0; mi < 4; mi++)                                          \
            _Pragma("unroll")                                                   \
            for (int p = 0; p < 4; p++) {                                       \
                MMA_F16(acc[mi][2 * p],     af[buf][mi], bq[buf][p]);           \
                MMA_F16(acc[mi][2 * p + 1], af[buf][mi], bq[buf][p] + 2);       \
            }                                                                   \
    } while (0)

    load_stage(0, 0);  CP_COMMIT();
    load_stage(1, 64); CP_COMMIT();
    CP_WAIT1();
    __syncthreads();

    const int nK = K / 64;
    int cur = 0;
    LD_FRAG(0, 0u, 0);

    for (int kt = 0; kt < nK; kt++) {
        const uint32_t sOff = (uint32_t)cur * stageBytes;
#pragma unroll
        for (int ks = 0; ks < 4; ks++) {
            const int cb = ks & 1;
            if (ks < 3) {
                if (cb) LD_FRAG(0, sOff, ks + 1);
                else    LD_FRAG(1, sOff, ks + 1);
            }
            if (cb) DO_MMA(1); else DO_MMA(0);
        }
        __syncthreads();
        if (kt + 2 < nK) load_stage(cur, (kt + 2) * 64);
        CP_COMMIT();
        CP_WAIT1();
        __syncthreads();
        cur ^= 1;
        if (kt + 1 < nK)
            LD_FRAG(0, (uint32_t)cur * stageBytes, 0);
    }
#undef LD_FRAG
#undef DO_MMA
}

// ---------------- proj GEMM: fp32 output ------------------------------------
__global__ __launch_bounds__(128, 2) void gemm_f16(const __half* __restrict__ A,
                                                   const __half* __restrict__ Bm,
                                                   float* __restrict__ Cm,
                                                   int M, int N, int K)
{
    extern __shared__ __half hsm[];
    __half* As = hsm;
    __half* Bs = hsm + 2 * HS_SZ;

    const int tid  = threadIdx.x;
    const int warp = tid >> 5;
    const int lane = tid & 31;
    const int g    = lane >> 2;
    const int tg   = lane & 3;
    const int lm8  = lane & 7;
    const int lq   = lane >> 3;
    const int wm   = (warp >> 1) * 64;
    const int wn   = (warp & 1) * 64;
    const int m0   = blockIdx.y * 128;
    const int n0   = blockIdx.x * 128;

    const uint32_t aBase = smem_u32(As) + (uint32_t)((wm + lm8 + ((lq & 1) << 3)) * HSTR) * 2
                                        + ((uint32_t)(lq >> 1) << 4);
    const uint32_t bBase = smem_u32(Bs) + (uint32_t)((wn + lm8 + ((lq >> 1) << 3)) * HSTR) * 2
                                        + ((uint32_t)(lq & 1) << 4);

    float acc[4][8][4];
    gemm_mainloop(A, Bm, As, Bs, m0, n0, K, tid, aBase, bBase, acc);

#pragma unroll
    for (int mi = 0; mi < 4; mi++) {
#pragma unroll
        for (int ni = 0; ni < 8; ni++) {
            const int r = m0 + wm + mi * 16 + g;
            const int c = n0 + wn + ni * 8 + 2 * tg;
            float2 v0 = {acc[mi][ni][0], acc[mi][ni][1]};
            float2 v1 = {acc[mi][ni][2], acc[mi][ni][3]};
            *(float2*)&Cm[(size_t)r * N + c]       = v0;
            *(float2*)&Cm[(size_t)(r + 8) * N + c] = v1;
        }
    }
}

// ---------------- QKV GEMM with fused RoPE/split epilogue --------------------
// N-tile (128) == head width: each CTA's output tile is one head-slice of
// q, k or v. Stage acc through smem (fp32), apply rope, write fp16 directly.
__global__ __launch_bounds__(128, 2) void gemm_qkv(const __half* __restrict__ A,
                                                   const __half* __restrict__ Bm,
                                                   const float* __restrict__ gain,
                                                   const float* __restrict__ cosb,
                                                   const float* __restrict__ sinb)
{
    extern __shared__ __half hsm[];
    __half* As = hsm;
    __half* Bs = hsm + 2 * HS_SZ;

    const int tid  = threadIdx.x;
    const int warp = tid >> 5;
    const int lane = tid & 31;
    const int g    = lane >> 2;
    const int tg   = lane & 3;
    const int lm8  = lane & 7;
    const int lq   = lane >> 3;
    const int wm   = (warp >> 1) * 64;
    const int wn   = (warp & 1) * 64;
    const int m0   = blockIdx.y * 128;
    const int n0   = blockIdx.x * 128;

    const uint32_t aBase = smem_u32(As) + (uint32_t)((wm + lm8 + ((lq & 1) << 3)) * HSTR) * 2
                                        + ((uint32_t)(lq >> 1) << 4);
    const uint32_t bBase = smem_u32(Bs) + (uint32_t)((wn + lm8 + ((lq >> 1) << 3)) * HSTR) * 2
                                        + ((uint32_t)(lq & 1) << 4);

    float acc[4][8][4];
    gemm_mainloop(A, Bm, As, Bs, m0, n0, C_, tid, aBase, bBase, acc);

    // stage fp32 tile in smem (reuse; all warps past final mainloop barrier)
    float* st = (float*)hsm;             // [128][TSTR], 67.6 KB < 73.7 KB
#pragma unroll
    for (int mi = 0; mi < 4; mi++) {
#pragma unroll
        for (int ni = 0; ni < 8; ni++) {
            const int r0 = wm + mi * 16 + g;
            const int c  = wn + ni * 8 + 2 * tg;
            *(float2*)&st[r0 * TSTR + c]       = make_float2(acc[mi][ni][0], acc[mi][ni][1]);
            *(float2*)&st[(r0 + 8) * TSTR + c] = make_float2(acc[mi][ni][2], acc[mi][ni][3]);
        }
    }
    __syncthreads();

    const int sel = n0 >> 11;            // 0=q, 1=k, 2=v
    const int h   = (n0 & 2047) >> 7;    // head index
    const float gn = gain[h] * rsqrtf((float)D_) * 1.4426950408889634f;

    // 128 rows x 64 pairs, 128 threads -> 64 pairs each
#pragma unroll 4
    for (int i = 0; i < 64; i++) {
        int p   = tid + i * 128;
        int row = p >> 6;
        int d   = p & 63;
        int grow = m0 + row;
        int t  = grow & (T_ - 1);
        int bb = grow >> 11;
        float s0 = st[row * TSTR + d];
        float s1 = st[row * TSTR + d + 64];
        size_t ob = ((size_t)((bb * H_ + h) * T_ + t)) * D_;
        if (sel == 0) {
            float c = cosb[t * 64 + d], s = sinb[t * 64 + d];
            g_q[ob + d]      = __float2half_rn((s0 * c - s1 * s) * gn);
            g_q[ob + d + 64] = __float2half_rn((s1 * c + s0 * s) * gn);
        } else if (sel == 1) {
            float c = cosb[t * 64 + d], s = sinb[t * 64 + d];
            g_k[ob + d]      = __float2half_rn(s0 * c - s1 * s);
            g_k[ob + d + 64] = __float2half_rn(s1 * c + s0 * s);
        } else {
            g_v[ob + d]      = __float2half_rn(s0);
            g_v[ob + d + 64] = __float2half_rn(s1);
        }
    }
}

// ---------------- fp16 flash attention: 64x64 tiles, 128 thr, 2 CTAs/SM ------
#define QH 136    // halves per row (272B stride, conflict-free)

__global__ __launch_bounds__(128, 2) void attn_tc(__half* __restrict__ Y)
{
    extern __shared__ __half ham[];
    __half* sQ = ham;                        // [64][QH]
    __half* sK = ham + 64 * QH;              // [64][QH]
    __half* sV = ham + 128 * QH;             // [64][QH]

    const int tid  = threadIdx.x;
    const int warp = tid >> 5;               // 0..3
    const int lane = tid & 31;
    const int g    = lane >> 2;
    const int tg   = lane & 3;
    const int lm8  = lane & 7;
    const int lq   = lane >> 3;
    const int qb = (T_ / 64 - 1) - blockIdx.x;   // LPT
    const int h  = blockIdx.y;
    const int b  = blockIdx.z;
    const int q0 = qb * 64;
    const size_t bh = ((size_t)(b * H_ + h)) * T_ * D_;

    const uint32_t qAddr = smem_u32(sQ)
        + (uint32_t)((16 * warp + lm8 + ((lq & 1) << 3)) * QH) * 2
        + ((uint32_t)(lq >> 1) << 4);
    const uint32_t kAddr = smem_u32(sK)
        + (uint32_t)((lm8 + ((lq >> 1) << 3)) * QH) * 2
        + ((uint32_t)(lq & 1) << 4);
    const uint32_t vAddr = smem_u32(sV)
        + (uint32_t)((lm8 + ((lq & 1) << 3)) * QH) * 2
        + ((uint32_t)(lq >> 1) << 4);

    auto load_k = [&](int k0) {
#pragma unroll
        for (int i = 0; i < 8; i++) {
            int e = tid + i * 128;
            int row = e >> 4;
            int col = (e & 15) * 8;
            cp16(&sK[row * QH + col], g_k + bh + (size_t)(k0 + row) * D_ + col);
        }
    };
    auto load_v = [&](int k0) {
#pragma unroll
        for (int i = 0; i < 8; i++) {
            int e = tid + i * 128;
            int row = e >> 4;
            int col = (e & 15) * 8;
            cp16(&sV[row * QH + col], g_v + bh + (size_t)(k0 + row) * D_ + col);
        }
    };

    load_k(0); CP_COMMIT();
    for (int i = 0; i < 8; i++) {
        int e = tid + i * 128;
        int row = e >> 4;
        int col = (e & 15) * 8;
        *(uint4*)&sQ[row * QH + col] = *(const uint4*)(g_q + bh + (size_t)(q0 + row) * D_ + col);
    }
    __syncthreads();

    uint32_t qf[8][4];
#pragma unroll
    for (int ks = 0; ks < 8; ks++)
        LDSM_X4(qf[ks], qAddr + ks * 32);

    float yacc[16][4];
#pragma unroll
    for (int nt = 0; nt < 16; nt++)
#pragma unroll
        for (int c = 0; c < 4; c++) yacc[nt][c] = 0.f;
    float m0 = -1e30f, m1 = -1e30f, l0 = 0.f, l1 = 0.f;

    for (int kt = 0; kt <= qb; kt++) {
        const int k0 = kt * 64;

        CP_WAIT0();
        __syncthreads();

        load_v(k0); CP_COMMIT();

        float sacc[8][4];
#pragma unroll
        for (int nt = 0; nt < 8; nt++)
#pragma unroll
            for (int c = 0; c < 4; c++) sacc[nt][c] = 0.f;

#pragma unroll
        for (int ks = 0; ks < 8; ks++) {
#pragma unroll
            for (int p = 0; p < 4; p++) {
                uint32_t bqv[4];
                LDSM_X4(bqv, kAddr + (uint32_t)(p * 16 * QH * 2) + ks * 32);
                MMA_F16(sacc[2 * p],     qf[ks], bqv);
                MMA_F16(sacc[2 * p + 1], qf[ks], bqv + 2);
            }
        }

        if (kt == qb) {
            const int r0g = q0 + 16 * warp + g;
            const int r1g = r0g + 8;
#pragma unroll
            for (int nt = 0; nt < 8; nt++) {
                int c0 = k0 + nt * 8 + 2 * tg;
                if (c0     > r0g) sacc[nt][0] = -1e30f;
                if (c0 + 1 > r0g) sacc[nt][1] = -1e30f;
                if (c0     > r1g) sacc[nt][2] = -1e30f;
                if (c0 + 1 > r1g) sacc[nt][3] = -1e30f;
            }
        }

        float mx0 = -1e30f, mx1 = -1e30f;
#pragma unroll
        for (int nt = 0; nt < 8; nt++) {
            mx0 = fmaxf(mx0, fmaxf(sacc[nt][0], sacc[nt][1]));
            mx1 = fmaxf(mx1, fmaxf(sacc[nt][2], sacc[nt][3]));
        }
        mx0 = fmaxf(mx0, __shfl_xor_sync(0xffffffffu, mx0, 1));
        mx0 = fmaxf(mx0, __shfl_xor_sync(0xffffffffu, mx0, 2));
        mx1 = fmaxf(mx1, __shfl_xor_sync(0xffffffffu, mx1, 1));
        mx1 = fmaxf(mx1, __shfl_xor_sync(0xffffffffu, mx1, 2));

        float nm0 = fmaxf(m0, mx0), nm1 = fmaxf(m1, mx1);
        float cf0 = exp2x(m0 - nm0), cf1 = exp2x(m1 - nm1);
        m0 = nm0; m1 = nm1;

        float rs0 = 0.f, rs1 = 0.f;
#pragma unroll
        for (int nt = 0; nt < 8; nt++) {
            sacc[nt][0] = exp2x(sacc[nt][0] - nm0);
            sacc[nt][1] = exp2x(sacc[nt][1] - nm0);
            sacc[nt][2] = exp2x(sacc[nt][2] - nm1);
            sacc[nt][3] = exp2x(sacc[nt][3] - nm1);
            rs0 += sacc[nt][0] + sacc[nt][1];
            rs1 += sacc[nt][2] + sacc[nt][3];
        }
        rs0 += __shfl_xor_sync(0xffffffffu, rs0, 1);
        rs0 += __shfl_xor_sync(0xffffffffu, rs0, 2);
        rs1 += __shfl_xor_sync(0xffffffffu, rs1, 1);
        rs1 += __shfl_xor_sync(0xffffffffu, rs1, 2);
        l0 = l0 * cf0 + rs0;
        l1 = l1 * cf1 + rs1;

#pragma unroll
        for (int nt = 0; nt < 16; nt++) {
            yacc[nt][0] *= cf0; yacc[nt][1] *= cf0;
            yacc[nt][2] *= cf1; yacc[nt][3] *= cf1;
        }

        uint32_t pf[4][4];
#pragma unroll
        for (int ks = 0; ks < 4; ks++) {
            pf[ks][0] = packh2(sacc[2 * ks][0],     sacc[2 * ks][1]);
            pf[ks][1] = packh2(sacc[2 * ks][2],     sacc[2 * ks][3]);
            pf[ks][2] = packh2(sacc[2 * ks + 1][0], sacc[2 * ks + 1][1]);
            pf[ks][3] = packh2(sacc[2 * ks + 1][2], sacc[2 * ks + 1][3]);
        }

        CP_WAIT0();
        __syncthreads();

        if (kt < qb) { load_k(k0 + 64); CP_COMMIT(); }

#pragma unroll
        for (int ks = 0; ks < 4; ks++) {
#pragma unroll
            for (int p = 0; p < 8; p++) {
                uint32_t bqv[4];
                LDSM_X4_T(bqv, vAddr + (uint32_t)(ks * 16 * QH * 2) + p * 32);
                MMA_F16(yacc[2 * p],     pf[ks], bqv);
                MMA_F16(yacc[2 * p + 1], pf[ks], bqv + 2);
            }
        }
    }

    const float inv0 = 1.f / l0;
    const float inv1 = 1.f / l1;
    const int r0g = q0 + 16 * warp + g;
    const int r1g = r0g + 8;
#pragma unroll
    for (int nt = 0; nt < 16; nt++) {
        int col = h * D_ + nt * 8 + 2 * tg;
        *(__half2*)&Y[(size_t)(b * T_ + r0g) * C_ + col] =
            __floats2half2_rn(yacc[nt][0] * inv0, yacc[nt][1] * inv0);
        *(__half2*)&Y[(size_t)(b * T_ + r1g) * C_ + col] =
            __floats2half2_rn(yacc[nt][2] * inv1, yacc[nt][3] * inv1);
    }
}

// ---------------- launch ----------------
extern "C" void kernel_launch(void* const* d_in, const int* in_sizes, int n_in,
                              void* d_out, int out_size)
{
    const float* x     = (const float*)d_in[0];
    const float* Wqkv  = (const float*)d_in[1];
    const float* Wproj = (const float*)d_in[2];
    const float* gain  = (const float*)d_in[3];
    const float* cosb  = (const float*)d_in[4];
    const float* sinb  = (const float*)d_in[5];
    float* out = (float*)d_out;

    __half *y, *xh, *wq, *wp;
    cudaGetSymbolAddress((void**)&y,   g_y);
    cudaGetSymbolAddress((void**)&xh,  g_xh);
    cudaGetSymbolAddress((void**)&wq,  g_wq);
    cudaGetSymbolAddress((void**)&wp,  g_wp);

    const size_t gemm_smem = (size_t)4 * HS_SZ * sizeof(__half);   // 73728
    cudaFuncSetAttribute(gemm_f16, cudaFuncAttributeMaxDynamicSharedMemorySize, (int)gemm_smem);
    cudaFuncSetAttribute(gemm_qkv, cudaFuncAttributeMaxDynamicSharedMemorySize, (int)gemm_smem);

    // 0) convert inputs to fp16
    {
        int n8x = (B_ * T_ * C_) / 8;
        cvt_f16_kernel<<<(n8x + 255) / 256, 256>>>((const float4*)x, (uint4*)xh, n8x);
        int n8q = (F_ * C_) / 8;
        cvt_f16_kernel<<<(n8q + 255) / 256, 256>>>((const float4*)Wqkv, (uint4*)wq, n8q);
        int n8p = (C_ * C_) / 8;
        cvt_f16_kernel<<<(n8p + 255) / 256, 256>>>((const float4*)Wproj, (uint4*)wp, n8p);
    }

    // 1) QKV GEMM with fused RoPE/split/gain epilogue -> g_q/g_k/g_v (fp16)
    {
        dim3 grid(F_ / 128, (B_ * T_) / 128);
        gemm_qkv<<<grid, 128, gemm_smem>>>(xh, wq, gain, cosb, sinb);
    }

    // 2) attention: 64x64 tiles, 128 threads, 2 CTAs/SM
    {
        size_t smem = (size_t)3 * 64 * QH * sizeof(__half);   // 52224
        cudaFuncSetAttribute(attn_tc, cudaFuncAttributeMaxDynamicSharedMemorySize, (int)smem);
        dim3 grid(T_ / 64, H_, B_);
        attn_tc<<<grid, 128, smem>>>(y);
    }

    // 3) output projection
    {
        dim3 grid(C_ / 128, (B_ * T_) / 128);
        gemm_f16<<<grid, 128, gemm_smem>>>(y, wp, out, B_ * T_, C_, C_);
    }
}

// round 16
// speedup vs baseline: 1.1054x; 1.1054x over previous
#include <cuda_runtime.h>
#include <cuda_fp16.h>
#include <math.h>
#include <float.h>
#include <stdint.h>

#define B_ 2
#define T_ 2048
#define C_ 2048
#define H_ 16
#define D_ 128
#define F_ (3*C_)

// ---------------- scratch ----------------
__device__ __half g_q[(size_t)B_ * H_ * T_ * D_];   // fp16 (scaled by gain/sqrtD*log2e)
__device__ __half g_k[(size_t)B_ * H_ * T_ * D_];
__device__ __half g_v[(size_t)B_ * H_ * T_ * D_];
__device__ __half g_y[(size_t)B_ * T_ * C_];
__device__ __half g_xh[(size_t)B_ * T_ * C_];       // fp16 x
__device__ __half g_wq[(size_t)F_ * C_];            // fp16 Wqkv
__device__ __half g_wp[(size_t)C_ * C_];            // fp16 Wproj

// ---------------- helpers ----------------
#define MMA_F16(c, a, b)                                                      \
  asm volatile(                                                               \
      "mma.sync.aligned.m16n8k16.row.col.f32.f16.f16.f32 "                    \
      "{%0,%1,%2,%3}, {%4,%5,%6,%7}, {%8,%9}, {%0,%1,%2,%3};"                 \
      : "+f"((c)[0]), "+f"((c)[1]), "+f"((c)[2]), "+f"((c)[3])                \
      : "r"((a)[0]), "r"((a)[1]), "r"((a)[2]), "r"((a)[3]),                   \
        "r"((b)[0]), "r"((b)[1]))

#define LDSM_X4(r, addr)                                                      \
  asm volatile("ldmatrix.sync.aligned.m8n8.x4.shared.b16 {%0,%1,%2,%3}, [%4];"\
      : "=r"((r)[0]), "=r"((r)[1]), "=r"((r)[2]), "=r"((r)[3])                \
      : "r"(addr))

#define LDSM_X4_T(r, addr)                                                    \
  asm volatile("ldmatrix.sync.aligned.m8n8.x4.trans.shared.b16 {%0,%1,%2,%3}, [%4];"\
      : "=r"((r)[0]), "=r"((r)[1]), "=r"((r)[2]), "=r"((r)[3])                \
      : "r"(addr))

__device__ __forceinline__ uint32_t smem_u32(const void* p) {
    return (uint32_t)__cvta_generic_to_shared(p);
}
__device__ __forceinline__ void cp16(void* sdst, const void* gsrc) {
    uint32_t s = smem_u32(sdst);
    asm volatile("cp.async.cg.shared.global [%0], [%1], 16;" :: "r"(s), "l"(gsrc));
}
#define CP_COMMIT() asm volatile("cp.async.commit_group;" ::)
#define CP_WAIT1()  asm volatile("cp.async.wait_group 1;" ::)
#define CP_WAIT0()  asm volatile("cp.async.wait_group 0;" ::)

__device__ __forceinline__ uint32_t packh2(float x, float y) {
    __half2 h = __floats2half2_rn(x, y);
    return *(uint32_t*)&h;
}
__device__ __forceinline__ float exp2x(float x) {
    float y; asm("ex2.approx.ftz.f32 %0, %1;" : "=f"(y) : "f"(x)); return y;
}

// ---------------- fp32 -> fp16 convert (8 elems/thread) ----------------
__global__ __launch_bounds__(256) void cvt_f16_kernel(const float4* __restrict__ src,
                                                      uint4* __restrict__ dst, int n8)
{
    int i = blockIdx.x * blockDim.x + threadIdx.x;
    if (i < n8) {
        float4 a = src[2 * i];
        float4 b = src[2 * i + 1];
        __half2 h0 = __floats2half2_rn(a.x, a.y);
        __half2 h1 = __floats2half2_rn(a.z, a.w);
        __half2 h2 = __floats2half2_rn(b.x, b.y);
        __half2 h3 = __floats2half2_rn(b.z, b.w);
        uint4 o = {*(uint32_t*)&h0, *(uint32_t*)&h1, *(uint32_t*)&h2, *(uint32_t*)&h3};
        dst[i] = o;
    }
}

// ---------------- shared GEMM mainloop (CTA 128x128, 4 warps 64x64, KS=64) ---
#define HSTR 72
#define HS_SZ (128 * HSTR)
#define TSTR 132   // fp32 epilogue staging stride

__device__ __forceinline__ void gemm_mainloop(
    const __half* __restrict__ A, const __half* __restrict__ Bm,
    __half* As, __half* Bs, int m0, int n0, int K, int tid,
    uint32_t aBase, uint32_t bBase, float acc[4][8][4])
{
#pragma unroll
    for (int mi = 0; mi < 4; mi++)
#pragma unroll
        for (int ni = 0; ni < 8; ni++)
#pragma unroll
            for (int c = 0; c < 4; c++) acc[mi][ni][c] = 0.f;

    uint32_t af[2][4][4], bq[2][4][4];
    const uint32_t stageBytes = HS_SZ * 2;

    auto load_stage = [&](int s, int k0) {
#pragma unroll
        for (int t = 0; t < 8; t++) {
            int cid = tid + t * 128;
            int row = cid >> 3;
            int ch8 = (cid & 7) * 8;
            cp16(&As[(size_t)s * HS_SZ + row * HSTR + ch8],
                 A + (size_t)(m0 + row) * K + k0 + ch8);
            cp16(&Bs[(size_t)s * HS_SZ + row * HSTR + ch8],
                 Bm + (size_t)(n0 + row) * K + k0 + ch8);
        }
    };

#define LD_FRAG(buf, sOff, ks)                                                  \
    do {                                                                        \
        _Pragma("unroll")                                                       \
        for (int mi = 0; mi < 4; mi++)                                          \
            LDSM_X4(af[buf][mi], aBase + (sOff) + (uint32_t)(mi * 16 * HSTR * 2) + (ks) * 32); \
        _Pragma("unroll")                                                       \
        for (int p = 0; p < 4; p++)                                             \
            LDSM_X4(bq[buf][p], bBase + (sOff) + (uint32_t)(p * 16 * HSTR * 2) + (ks) * 32);   \
    } while (0)

#define DO_MMA(buf)                                                             \
    do {                                                                        \
        _Pragma("unroll")                                                       \
        for (int mi = 0; mi < 4; mi++)                                          \
            _Pragma("unroll")                                                   \
            for (int p = 0; p < 4; p++) {                                       \
                MMA_F16(acc[mi][2 * p],     af[buf][mi], bq[buf][p]);           \
                MMA_F16(acc[mi][2 * p + 1], af[buf][mi], bq[buf][p] + 2);       \
            }                                                                   \
    } while (0)

    load_stage(0, 0);  CP_COMMIT();
    load_stage(1, 64); CP_COMMIT();
    CP_WAIT1();
    __syncthreads();

    const int nK = K / 64;
    int cur = 0;
    LD_FRAG(0, 0u, 0);

    for (int kt = 0; kt < nK; kt++) {
        const uint32_t sOff = (uint32_t)cur * stageBytes;
#pragma unroll
        for (int ks = 0; ks < 4; ks++) {
            const int cb = ks & 1;
            if (ks < 3) {
                if (cb) LD_FRAG(0, sOff, ks + 1);
                else    LD_FRAG(1, sOff, ks + 1);
            }
            if (cb) DO_MMA(1); else DO_MMA(0);
        }
        __syncthreads();
        if (kt + 2 < nK) load_stage(cur, (kt + 2) * 64);
        CP_COMMIT();
        CP_WAIT1();
        __syncthreads();
        cur ^= 1;
        if (kt + 1 < nK)
            LD_FRAG(0, (uint32_t)cur * stageBytes, 0);
    }
#undef LD_FRAG
#undef DO_MMA
}

// ---------------- proj GEMM: fp32 output ------------------------------------
__global__ __launch_bounds__(128, 2) void gemm_f16(const __half* __restrict__ A,
                                                   const __half* __restrict__ Bm,
                                                   float* __restrict__ Cm,
                                                   int M, int N, int K)
{
    extern __shared__ __half hsm[];
    __half* As = hsm;
    __half* Bs = hsm + 2 * HS_SZ;

    const int tid  = threadIdx.x;
    const int warp = tid >> 5;
    const int lane = tid & 31;
    const int g    = lane >> 2;
    const int tg   = lane & 3;
    const int lm8  = lane & 7;
    const int lq   = lane >> 3;
    const int wm   = (warp >> 1) * 64;
    const int wn   = (warp & 1) * 64;
    const int m0   = blockIdx.y * 128;
    const int n0   = blockIdx.x * 128;

    const uint32_t aBase = smem_u32(As) + (uint32_t)((wm + lm8 + ((lq & 1) << 3)) * HSTR) * 2
                                        + ((uint32_t)(lq >> 1) << 4);
    const uint32_t bBase = smem_u32(Bs) + (uint32_t)((wn + lm8 + ((lq >> 1) << 3)) * HSTR) * 2
                                        + ((uint32_t)(lq & 1) << 4);

    float acc[4][8][4];
    gemm_mainloop(A, Bm, As, Bs, m0, n0, K, tid, aBase, bBase, acc);

#pragma unroll
    for (int mi = 0; mi < 4; mi++) {
#pragma unroll
        for (int ni = 0; ni < 8; ni++) {
            const int r = m0 + wm + mi * 16 + g;
            const int c = n0 + wn + ni * 8 + 2 * tg;
            float2 v0 = {acc[mi][ni][0], acc[mi][ni][1]};
            float2 v1 = {acc[mi][ni][2], acc[mi][ni][3]};
            *(float2*)&Cm[(size_t)r * N + c]       = v0;
            *(float2*)&Cm[(size_t)(r + 8) * N + c] = v1;
        }
    }
}

// ---------------- QKV GEMM with fused RoPE/split epilogue --------------------
// N-tile (128) == head width: each CTA's output tile is one head-slice of
// q, k or v. Stage acc through smem (fp32), apply rope, write fp16 (16B stores).
__global__ __launch_bounds__(128, 2) void gemm_qkv(const __half* __restrict__ A,
                                                   const __half* __restrict__ Bm,
                                                   const float* __restrict__ gain,
                                                   const float* __restrict__ cosb,
                                                   const float* __restrict__ sinb)
{
    extern __shared__ __half hsm[];
    __half* As = hsm;
    __half* Bs = hsm + 2 * HS_SZ;

    const int tid  = threadIdx.x;
    const int warp = tid >> 5;
    const int lane = tid & 31;
    const int g    = lane >> 2;
    const int tg   = lane & 3;
    const int lm8  = lane & 7;
    const int lq   = lane >> 3;
    const int wm   = (warp >> 1) * 64;
    const int wn   = (warp & 1) * 64;
    const int m0   = blockIdx.y * 128;
    const int n0   = blockIdx.x * 128;

    const uint32_t aBase = smem_u32(As) + (uint32_t)((wm + lm8 + ((lq & 1) << 3)) * HSTR) * 2
                                        + ((uint32_t)(lq >> 1) << 4);
    const uint32_t bBase = smem_u32(Bs) + (uint32_t)((wn + lm8 + ((lq >> 1) << 3)) * HSTR) * 2
                                        + ((uint32_t)(lq & 1) << 4);

    float acc[4][8][4];
    gemm_mainloop(A, Bm, As, Bs, m0, n0, C_, tid, aBase, bBase, acc);

    // stage fp32 tile in smem (reuse; all warps past final mainloop barrier)
    float* st = (float*)hsm;             // [128][TSTR], 67.6 KB < 73.7 KB
#pragma unroll
    for (int mi = 0; mi < 4; mi++) {
#pragma unroll
        for (int ni = 0; ni < 8; ni++) {
            const int r0 = wm + mi * 16 + g;
            const int c  = wn + ni * 8 + 2 * tg;
            *(float2*)&st[r0 * TSTR + c]       = make_float2(acc[mi][ni][0], acc[mi][ni][1]);
            *(float2*)&st[(r0 + 8) * TSTR + c] = make_float2(acc[mi][ni][2], acc[mi][ni][3]);
        }
    }
    __syncthreads();

    const int sel = n0 >> 11;            // 0=q, 1=k, 2=v
    const int h   = (n0 & 2047) >> 7;    // head index
    const float gn = gain[h] * rsqrtf((float)D_) * 1.4426950408889634f;

    // vectorized epilogue: each thread handles 8 consecutive d in one row.
    // 128 rows x 8 groups = 1024 items / 128 threads = 8 iterations.
    // Stores: uint4 (16B), 8 threads cover 128B contiguous — fully coalesced.
#pragma unroll
    for (int i = 0; i < 8; i++) {
        int p   = tid + i * 128;
        int row = p >> 3;
        int d0  = (p & 7) * 8;
        int grow = m0 + row;
        int t  = grow & (T_ - 1);
        int bb = grow >> 11;
        size_t ob = ((size_t)((bb * H_ + h) * T_ + t)) * D_;

        float lo[8], hi[8];
        *(float4*)&lo[0] = *(float4*)&st[row * TSTR + d0];
        *(float4*)&lo[4] = *(float4*)&st[row * TSTR + d0 + 4];
        *(float4*)&hi[0] = *(float4*)&st[row * TSTR + d0 + 64];
        *(float4*)&hi[4] = *(float4*)&st[row * TSTR + d0 + 68];

        __half olo[8], ohi[8];
        if (sel == 2) {
#pragma unroll
            for (int j = 0; j < 8; j++) {
                olo[j] = __float2half_rn(lo[j]);
                ohi[j] = __float2half_rn(hi[j]);
            }
            *(uint4*)&g_v[ob + d0]      = *(uint4*)&olo[0];
            *(uint4*)&g_v[ob + d0 + 64] = *(uint4*)&ohi[0];
        } else {
            float cs[8], sn[8];
            *(float4*)&cs[0] = *(const float4*)&cosb[t * 64 + d0];
            *(float4*)&cs[4] = *(const float4*)&cosb[t * 64 + d0 + 4];
            *(float4*)&sn[0] = *(const float4*)&sinb[t * 64 + d0];
            *(float4*)&sn[4] = *(const float4*)&sinb[t * 64 + d0 + 4];
            if (sel == 0) {
#pragma unroll
                for (int j = 0; j < 8; j++) {
                    olo[j] = __float2half_rn((lo[j] * cs[j] - hi[j] * sn[j]) * gn);
                    ohi[j] = __float2half_rn((hi[j] * cs[j] + lo[j] * sn[j]) * gn);
                }
                *(uint4*)&g_q[ob + d0]      = *(uint4*)&olo[0];
                *(uint4*)&g_q[ob + d0 + 64] = *(uint4*)&ohi[0];
            } else {
#pragma unroll
                for (int j = 0; j < 8; j++) {
                    olo[j] = __float2half_rn(lo[j] * cs[j] - hi[j] * sn[j]);
                    ohi[j] = __float2half_rn(hi[j] * cs[j] + lo[j] * sn[j]);
                }
                *(uint4*)&g_k[ob + d0]      = *(uint4*)&olo[0];
                *(uint4*)&g_k[ob + d0 + 64] = *(uint4*)&ohi[0];
            }
        }
    }
}

// ---------------- fp16 flash attention: 64x64 tiles, 128 thr, 2 CTAs/SM ------
#define QH 136    // halves per row (272B stride, conflict-free)

__global__ __launch_bounds__(128, 2) void attn_tc(__half* __restrict__ Y)
{
    extern __shared__ __half ham[];
    __half* sQ = ham;                        // [64][QH]
    __half* sK = ham + 64 * QH;              // [64][QH]
    __half* sV = ham + 128 * QH;             // [64][QH]

    const int tid  = threadIdx.x;
    const int warp = tid >> 5;               // 0..3
    const int lane = tid & 31;
    const int g    = lane >> 2;
    const int tg   = lane & 3;
    const int lm8  = lane & 7;
    const int lq   = lane >> 3;
    const int qb = (T_ / 64 - 1) - blockIdx.x;   // LPT
    const int h  = blockIdx.y;
    const int b  = blockIdx.z;
    const int q0 = qb * 64;
    const size_t bh = ((size_t)(b * H_ + h)) * T_ * D_;

    const uint32_t qAddr = smem_u32(sQ)
        + (uint32_t)((16 * warp + lm8 + ((lq & 1) << 3)) * QH) * 2
        + ((uint32_t)(lq >> 1) << 4);
    const uint32_t kAddr = smem_u32(sK)
        + (uint32_t)((lm8 + ((lq >> 1) << 3)) * QH) * 2
        + ((uint32_t)(lq & 1) << 4);
    const uint32_t vAddr = smem_u32(sV)
        + (uint32_t)((lm8 + ((lq & 1) << 3)) * QH) * 2
        + ((uint32_t)(lq >> 1) << 4);

    auto load_k = [&](int k0) {
#pragma unroll
        for (int i = 0; i < 8; i++) {
            int e = tid + i * 128;
            int row = e >> 4;
            int col = (e & 15) * 8;
            cp16(&sK[row * QH + col], g_k + bh + (size_t)(k0 + row) * D_ + col);
        }
    };
    auto load_v = [&](int k0) {
#pragma unroll
        for (int i = 0; i < 8; i++) {
            int e = tid + i * 128;
            int row = e >> 4;
            int col = (e & 15) * 8;
            cp16(&sV[row * QH + col], g_v + bh + (size_t)(k0 + row) * D_ + col);
        }
    };

    load_k(0); CP_COMMIT();
    for (int i = 0; i < 8; i++) {
        int e = tid + i * 128;
        int row = e >> 4;
        int col = (e & 15) * 8;
        *(uint4*)&sQ[row * QH + col] = *(const uint4*)(g_q + bh + (size_t)(q0 + row) * D_ + col);
    }
    __syncthreads();

    uint32_t qf[8][4];
#pragma unroll
    for (int ks = 0; ks < 8; ks++)
        LDSM_X4(qf[ks], qAddr + ks * 32);

    float yacc[16][4];
#pragma unroll
    for (int nt = 0; nt < 16; nt++)
#pragma unroll
        for (int c = 0; c < 4; c++) yacc[nt][c] = 0.f;
    float m0 = -1e30f, m1 = -1e30f, l0 = 0.f, l1 = 0.f;

    for (int kt = 0; kt <= qb; kt++) {
        const int k0 = kt * 64;

        CP_WAIT0();
        __syncthreads();

        load_v(k0); CP_COMMIT();

        float sacc[8][4];
#pragma unroll
        for (int nt = 0; nt < 8; nt++)
#pragma unroll
            for (int c = 0; c < 4; c++) sacc[nt][c] = 0.f;

#pragma unroll
        for (int ks = 0; ks < 8; ks++) {
#pragma unroll
            for (int p = 0; p < 4; p++) {
                uint32_t bqv[4];
                LDSM_X4(bqv, kAddr + (uint32_t)(p * 16 * QH * 2) + ks * 32);
                MMA_F16(sacc[2 * p],     qf[ks], bqv);
                MMA_F16(sacc[2 * p + 1], qf[ks], bqv + 2);
            }
        }

        if (kt == qb) {
            const int r0g = q0 + 16 * warp + g;
            const int r1g = r0g + 8;
#pragma unroll
            for (int nt = 0; nt < 8; nt++) {
                int c0 = k0 + nt * 8 + 2 * tg;
                if (c0     > r0g) sacc[nt][0] = -1e30f;
                if (c0 + 1 > r0g) sacc[nt][1] = -1e30f;
                if (c0     > r1g) sacc[nt][2] = -1e30f;
                if (c0 + 1 > r1g) sacc[nt][3] = -1e30f;
            }
        }

        float mx0 = -1e30f, mx1 = -1e30f;
#pragma unroll
        for (int nt = 0; nt < 8; nt++) {
            mx0 = fmaxf(mx0, fmaxf(sacc[nt][0], sacc[nt][1]));
            mx1 = fmaxf(mx1, fmaxf(sacc[nt][2], sacc[nt][3]));
        }
        mx0 = fmaxf(mx0, __shfl_xor_sync(0xffffffffu, mx0, 1));
        mx0 = fmaxf(mx0, __shfl_xor_sync(0xffffffffu, mx0, 2));
        mx1 = fmaxf(mx1, __shfl_xor_sync(0xffffffffu, mx1, 1));
        mx1 = fmaxf(mx1, __shfl_xor_sync(0xffffffffu, mx1, 2));

        float nm0 = fmaxf(m0, mx0), nm1 = fmaxf(m1, mx1);
        float cf0 = exp2x(m0 - nm0), cf1 = exp2x(m1 - nm1);
        m0 = nm0; m1 = nm1;

        float rs0 = 0.f, rs1 = 0.f;
#pragma unroll
        for (int nt = 0; nt < 8; nt++) {
            sacc[nt][0] = exp2x(sacc[nt][0] - nm0);
            sacc[nt][1] = exp2x(sacc[nt][1] - nm0);
            sacc[nt][2] = exp2x(sacc[nt][2] - nm1);
            sacc[nt][3] = exp2x(sacc[nt][3] - nm1);
            rs0 += sacc[nt][0] + sacc[nt][1];
            rs1 += sacc[nt][2] + sacc[nt][3];
        }
        rs0 += __shfl_xor_sync(0xffffffffu, rs0, 1);
        rs0 += __shfl_xor_sync(0xffffffffu, rs0, 2);
        rs1 += __shfl_xor_sync(0xffffffffu, rs1, 1);
        rs1 += __shfl_xor_sync(0xffffffffu, rs1, 2);
        l0 = l0 * cf0 + rs0;
        l1 = l1 * cf1 + rs1;

#pragma unroll
        for (int nt = 0; nt < 16; nt++) {
            yacc[nt][0] *= cf0; yacc[nt][1] *= cf0;
            yacc[nt][2] *= cf1; yacc[nt][3] *= cf1;
        }

        uint32_t pf[4][4];
#pragma unroll
        for (int ks = 0; ks < 4; ks++) {
            pf[ks][0] = packh2(sacc[2 * ks][0],     sacc[2 * ks][1]);
            pf[ks][1] = packh2(sacc[2 * ks][2],     sacc[2 * ks][3]);
            pf[ks][2] = packh2(sacc[2 * ks + 1][0], sacc[2 * ks + 1][1]);
            pf[ks][3] = packh2(sacc[2 * ks + 1][2], sacc[2 * ks + 1][3]);
        }

        CP_WAIT0();
        __syncthreads();

        if (kt < qb) { load_k(k0 + 64); CP_COMMIT(); }

#pragma unroll
        for (int ks = 0; ks < 4; ks++) {
#pragma unroll
            for (int p = 0; p < 8; p++) {
                uint32_t bqv[4];
                LDSM_X4_T(bqv, vAddr + (uint32_t)(ks * 16 * QH * 2) + p * 32);
                MMA_F16(yacc[2 * p],     pf[ks], bqv);
                MMA_F16(yacc[2 * p + 1], pf[ks], bqv + 2);
            }
        }
    }

    const float inv0 = 1.f / l0;
    const float inv1 = 1.f / l1;
    const int r0g = q0 + 16 * warp + g;
    const int r1g = r0g + 8;
#pragma unroll
    for (int nt = 0; nt < 16; nt++) {
        int col = h * D_ + nt * 8 + 2 * tg;
        *(__half2*)&Y[(size_t)(b * T_ + r0g) * C_ + col] =
            __floats2half2_rn(yacc[nt][0] * inv0, yacc[nt][1] * inv0);
        *(__half2*)&Y[(size_t)(b * T_ + r1g) * C_ + col] =
            __floats2half2_rn(yacc[nt][2] * inv1, yacc[nt][3] * inv1);
    }
}

// ---------------- launch ----------------
extern "C" void kernel_launch(void* const* d_in, const int* in_sizes, int n_in,
                              void* d_out, int out_size)
{
    const float* x     = (const float*)d_in[0];
    const float* Wqkv  = (const float*)d_in[1];
    const float* Wproj = (const float*)d_in[2];
    const float* gain  = (const float*)d_in[3];
    const float* cosb  = (const float*)d_in[4];
    const float* sinb  = (const float*)d_in[5];
    float* out = (float*)d_out;

    __half *y, *xh, *wq, *wp;
    cudaGetSymbolAddress((void**)&y,   g_y);
    cudaGetSymbolAddress((void**)&xh,  g_xh);
    cudaGetSymbolAddress((void**)&wq,  g_wq);
    cudaGetSymbolAddress((void**)&wp,  g_wp);

    const size_t gemm_smem = (size_t)4 * HS_SZ * sizeof(__half);   // 73728
    cudaFuncSetAttribute(gemm_f16, cudaFuncAttributeMaxDynamicSharedMemorySize, (int)gemm_smem);
    cudaFuncSetAttribute(gemm_qkv, cudaFuncAttributeMaxDynamicSharedMemorySize, (int)gemm_smem);

    // 0) convert inputs to fp16
    {
        int n8x = (B_ * T_ * C_) / 8;
        cvt_f16_kernel<<<(n8x + 255) / 256, 256>>>((const float4*)x, (uint4*)xh, n8x);
        int n8q = (F_ * C_) / 8;
        cvt_f16_kernel<<<(n8q + 255) / 256, 256>>>((const float4*)Wqkv, (uint4*)wq, n8q);
        int n8p = (C_ * C_) / 8;
        cvt_f16_kernel<<<(n8p + 255) / 256, 256>>>((const float4*)Wproj, (uint4*)wp, n8p);
    }

    // 1) QKV GEMM with fused RoPE/split/gain epilogue -> g_q/g_k/g_v (fp16)
    {
        dim3 grid(F_ / 128, (B_ * T_) / 128);
        gemm_qkv<<<grid, 128, gemm_smem>>>(xh, wq, gain, cosb, sinb);
    }

    // 2) attention: 64x64 tiles, 128 threads, 2 CTAs/SM
    {
        size_t smem = (size_t)3 * 64 * QH * sizeof(__half);   // 52224
        cudaFuncSetAttribute(attn_tc, cudaFuncAttributeMaxDynamicSharedMemorySize, (int)smem);
        dim3 grid(T_ / 64, H_, B_);
        attn_tc<<<grid, 128, smem>>>(y);
    }

    // 3) output projection
    {
        dim3 grid(C_ / 128, (B_ * T_) / 128);
        gemm_f16<<<grid, 128, gemm_smem>>>(y, wp, out, B_ * T_, C_, C_);
    }
}

// round 17
// speedup vs baseline: 1.1196x; 1.0129x over previous
#include <cuda_runtime.h>
#include <cuda_fp16.h>
#include <math.h>
#include <float.h>
#include <stdint.h>

#define B_ 2
#define T_ 2048
#define C_ 2048
#define H_ 16
#define D_ 128
#define F_ (3*C_)

// ---------------- scratch ----------------
__device__ __half g_q[(size_t)B_ * H_ * T_ * D_];   // fp16 (scaled by gain/sqrtD*log2e)
__device__ __half g_k[(size_t)B_ * H_ * T_ * D_];
__device__ __half g_v[(size_t)B_ * H_ * T_ * D_];
__device__ __half g_y[(size_t)B_ * T_ * C_];
__device__ __half g_xh[(size_t)B_ * T_ * C_];       // fp16 x
__device__ __half g_wq[(size_t)F_ * C_];            // fp16 Wqkv
__device__ __half g_wp[(size_t)C_ * C_];            // fp16 Wproj

// ---------------- helpers ----------------
#define MMA_F16(c, a, b)                                                      \
  asm volatile(                                                               \
      "mma.sync.aligned.m16n8k16.row.col.f32.f16.f16.f32 "                    \
      "{%0,%1,%2,%3}, {%4,%5,%6,%7}, {%8,%9}, {%0,%1,%2,%3};"                 \
      : "+f"((c)[0]), "+f"((c)[1]), "+f"((c)[2]), "+f"((c)[3])                \
      : "r"((a)[0]), "r"((a)[1]), "r"((a)[2]), "r"((a)[3]),                   \
        "r"((b)[0]), "r"((b)[1]))

#define LDSM_X4(r, addr)                                                      \
  asm volatile("ldmatrix.sync.aligned.m8n8.x4.shared.b16 {%0,%1,%2,%3}, [%4];"\
      : "=r"((r)[0]), "=r"((r)[1]), "=r"((r)[2]), "=r"((r)[3])                \
      : "r"(addr))

#define LDSM_X4_T(r, addr)                                                    \
  asm volatile("ldmatrix.sync.aligned.m8n8.x4.trans.shared.b16 {%0,%1,%2,%3}, [%4];"\
      : "=r"((r)[0]), "=r"((r)[1]), "=r"((r)[2]), "=r"((r)[3])                \
      : "r"(addr))

__device__ __forceinline__ uint32_t smem_u32(const void* p) {
    return (uint32_t)__cvta_generic_to_shared(p);
}
__device__ __forceinline__ void cp16(void* sdst, const void* gsrc) {
    uint32_t s = smem_u32(sdst);
    asm volatile("cp.async.cg.shared.global [%0], [%1], 16;" :: "r"(s), "l"(gsrc));
}
#define CP_COMMIT() asm volatile("cp.async.commit_group;" ::)
#define CP_WAIT1()  asm volatile("cp.async.wait_group 1;" ::)
#define CP_WAIT0()  asm volatile("cp.async.wait_group 0;" ::)

__device__ __forceinline__ uint32_t packh2(float x, float y) {
    __half2 h = __floats2half2_rn(x, y);
    return *(uint32_t*)&h;
}
__device__ __forceinline__ float exp2x(float x) {
    float y; asm("ex2.approx.ftz.f32 %0, %1;" : "=f"(y) : "f"(x)); return y;
}

// ---------------- fp32 -> fp16 convert (8 elems/thread) ----------------
__global__ __launch_bounds__(256) void cvt_f16_kernel(const float4* __restrict__ src,
                                                      uint4* __restrict__ dst, int n8)
{
    int i = blockIdx.x * blockDim.x + threadIdx.x;
    if (i < n8) {
        float4 a = src[2 * i];
        float4 b = src[2 * i + 1];
        __half2 h0 = __floats2half2_rn(a.x, a.y);
        __half2 h1 = __floats2half2_rn(a.z, a.w);
        __half2 h2 = __floats2half2_rn(b.x, b.y);
        __half2 h3 = __floats2half2_rn(b.z, b.w);
        uint4 o = {*(uint32_t*)&h0, *(uint32_t*)&h1, *(uint32_t*)&h2, *(uint32_t*)&h3};
        dst[i] = o;
    }
}

// ---------------- shared GEMM mainloop (CTA 128x128, 4 warps 64x64, KS=64) ---
#define HSTR 72
#define HS_SZ (128 * HSTR)
#define TSTR 132   // fp32 epilogue staging stride

__device__ __forceinline__ void gemm_mainloop(
    const __half* __restrict__ A, const __half* __restrict__ Bm,
    __half* As, __half* Bs, int m0, int n0, int K, int tid,
    uint32_t aBase, uint32_t bBase, float acc[4][8][4])
{
#pragma unroll
    for (int mi = 0; mi < 4; mi++)
#pragma unroll
        for (int ni = 0; ni < 8; ni++)
#pragma unroll
            for (int c = 0; c < 4; c++) acc[mi][ni][c] = 0.f;

    uint32_t af[2][4][4], bq[2][4][4];
    const uint32_t stageBytes = HS_SZ * 2;

    auto load_stage = [&](int s, int k0) {
#pragma unroll
        for (int t = 0; t < 8; t++) {
            int cid = tid + t * 128;
            int row = cid >> 3;
            int ch8 = (cid & 7) * 8;
            cp16(&As[(size_t)s * HS_SZ + row * HSTR + ch8],
                 A + (size_t)(m0 + row) * K + k0 + ch8);
            cp16(&Bs[(size_t)s * HS_SZ + row * HSTR + ch8],
                 Bm + (size_t)(n0 + row) * K + k0 + ch8);
        }
    };

#define LD_FRAG(buf, sOff, ks)                                                  \
    do {                                                                        \
        _Pragma("unroll")                                                       \
        for (int mi = 0; mi < 4; mi++)                                          \
            LDSM_X4(af[buf][mi], aBase + (sOff) + (uint32_t)(mi * 16 * HSTR * 2) + (ks) * 32); \
        _Pragma("unroll")                                                       \
        for (int p = 0; p < 4; p++)                                             \
            LDSM_X4(bq[buf][p], bBase + (sOff) + (uint32_t)(p * 16 * HSTR * 2) + (ks) * 32);   \
    } while (0)

#define DO_MMA(buf)                                                             \
    do {                                                                        \
        _Pragma("unroll")                                                       \
        for (int mi = 0; mi < 4; mi++)                                          \
            _Pragma("unroll")                                                   \
            for (int p = 0; p < 4; p++) {                                       \
                MMA_F16(acc[mi][2 * p],     af[buf][mi], bq[buf][p]);           \
                MMA_F16(acc[mi][2 * p + 1], af[buf][mi], bq[buf][p] + 2);       \
            }                                                                   \
    } while (0)

    load_stage(0, 0);  CP_COMMIT();
    load_stage(1, 64); CP_COMMIT();
    CP_WAIT1();
    __syncthreads();

    const int nK = K / 64;
    int cur = 0;
    LD_FRAG(0, 0u, 0);

    for (int kt = 0; kt < nK; kt++) {
        const uint32_t sOff = (uint32_t)cur * stageBytes;
#pragma unroll
        for (int ks = 0; ks < 4; ks++) {
            const int cb = ks & 1;
            if (ks < 3) {
                if (cb) LD_FRAG(0, sOff, ks + 1);
                else    LD_FRAG(1, sOff, ks + 1);
            }
            if (cb) DO_MMA(1); else DO_MMA(0);
        }
        __syncthreads();
        if (kt + 2 < nK) load_stage(cur, (kt + 2) * 64);
        CP_COMMIT();
        CP_WAIT1();
        __syncthreads();
        cur ^= 1;
        if (kt + 1 < nK)
            LD_FRAG(0, (uint32_t)cur * stageBytes, 0);
    }
#undef LD_FRAG
#undef DO_MMA
}

// ---------------- proj GEMM: fp32 output ------------------------------------
__global__ __launch_bounds__(128, 2) void gemm_f16(const __half* __restrict__ A,
                                                   const __half* __restrict__ Bm,
                                                   float* __restrict__ Cm,
                                                   int M, int N, int K)
{
    extern __shared__ __half hsm[];
    __half* As = hsm;
    __half* Bs = hsm + 2 * HS_SZ;

    const int tid  = threadIdx.x;
    const int warp = tid >> 5;
    const int lane = tid & 31;
    const int g    = lane >> 2;
    const int tg   = lane & 3;
    const int lm8  = lane & 7;
    const int lq   = lane >> 3;
    const int wm   = (warp >> 1) * 64;
    const int wn   = (warp & 1) * 64;
    const int m0   = blockIdx.y * 128;
    const int n0   = blockIdx.x * 128;

    const uint32_t aBase = smem_u32(As) + (uint32_t)((wm + lm8 + ((lq & 1) << 3)) * HSTR) * 2
                                        + ((uint32_t)(lq >> 1) << 4);
    const uint32_t bBase = smem_u32(Bs) + (uint32_t)((wn + lm8 + ((lq >> 1) << 3)) * HSTR) * 2
                                        + ((uint32_t)(lq & 1) << 4);

    float acc[4][8][4];
    gemm_mainloop(A, Bm, As, Bs, m0, n0, K, tid, aBase, bBase, acc);

#pragma unroll
    for (int mi = 0; mi < 4; mi++) {
#pragma unroll
        for (int ni = 0; ni < 8; ni++) {
            const int r = m0 + wm + mi * 16 + g;
            const int c = n0 + wn + ni * 8 + 2 * tg;
            float2 v0 = {acc[mi][ni][0], acc[mi][ni][1]};
            float2 v1 = {acc[mi][ni][2], acc[mi][ni][3]};
            *(float2*)&Cm[(size_t)r * N + c]       = v0;
            *(float2*)&Cm[(size_t)(r + 8) * N + c] = v1;
        }
    }
}

// ---------------- QKV GEMM with fused RoPE/split epilogue --------------------
__global__ __launch_bounds__(128, 2) void gemm_qkv(const __half* __restrict__ A,
                                                   const __half* __restrict__ Bm,
                                                   const float* __restrict__ gain,
                                                   const float* __restrict__ cosb,
                                                   const float* __restrict__ sinb)
{
    extern __shared__ __half hsm[];
    __half* As = hsm;
    __half* Bs = hsm + 2 * HS_SZ;

    const int tid  = threadIdx.x;
    const int warp = tid >> 5;
    const int lane = tid & 31;
    const int g    = lane >> 2;
    const int tg   = lane & 3;
    const int lm8  = lane & 7;
    const int lq   = lane >> 3;
    const int wm   = (warp >> 1) * 64;
    const int wn   = (warp & 1) * 64;
    const int m0   = blockIdx.y * 128;
    const int n0   = blockIdx.x * 128;

    const uint32_t aBase = smem_u32(As) + (uint32_t)((wm + lm8 + ((lq & 1) << 3)) * HSTR) * 2
                                        + ((uint32_t)(lq >> 1) << 4);
    const uint32_t bBase = smem_u32(Bs) + (uint32_t)((wn + lm8 + ((lq >> 1) << 3)) * HSTR) * 2
                                        + ((uint32_t)(lq & 1) << 4);

    float acc[4][8][4];
    gemm_mainloop(A, Bm, As, Bs, m0, n0, C_, tid, aBase, bBase, acc);

    float* st = (float*)hsm;             // [128][TSTR]
#pragma unroll
    for (int mi = 0; mi < 4; mi++) {
#pragma unroll
        for (int ni = 0; ni < 8; ni++) {
            const int r0 = wm + mi * 16 + g;
            const int c  = wn + ni * 8 + 2 * tg;
            *(float2*)&st[r0 * TSTR + c]       = make_float2(acc[mi][ni][0], acc[mi][ni][1]);
            *(float2*)&st[(r0 + 8) * TSTR + c] = make_float2(acc[mi][ni][2], acc[mi][ni][3]);
        }
    }
    __syncthreads();

    const int sel = n0 >> 11;            // 0=q, 1=k, 2=v
    const int h   = (n0 & 2047) >> 7;    // head index
    const float gn = gain[h] * rsqrtf((float)D_) * 1.4426950408889634f;

#pragma unroll
    for (int i = 0; i < 8; i++) {
        int p   = tid + i * 128;
        int row = p >> 3;
        int d0  = (p & 7) * 8;
        int grow = m0 + row;
        int t  = grow & (T_ - 1);
        int bb = grow >> 11;
        size_t ob = ((size_t)((bb * H_ + h) * T_ + t)) * D_;

        float lo[8], hi[8];
        *(float4*)&lo[0] = *(float4*)&st[row * TSTR + d0];
        *(float4*)&lo[4] = *(float4*)&st[row * TSTR + d0 + 4];
        *(float4*)&hi[0] = *(float4*)&st[row * TSTR + d0 + 64];
        *(float4*)&hi[4] = *(float4*)&st[row * TSTR + d0 + 68];

        __half olo[8], ohi[8];
        if (sel == 2) {
#pragma unroll
            for (int j = 0; j < 8; j++) {
                olo[j] = __float2half_rn(lo[j]);
                ohi[j] = __float2half_rn(hi[j]);
            }
            *(uint4*)&g_v[ob + d0]      = *(uint4*)&olo[0];
            *(uint4*)&g_v[ob + d0 + 64] = *(uint4*)&ohi[0];
        } else {
            float cs[8], sn[8];
            *(float4*)&cs[0] = *(const float4*)&cosb[t * 64 + d0];
            *(float4*)&cs[4] = *(const float4*)&cosb[t * 64 + d0 + 4];
            *(float4*)&sn[0] = *(const float4*)&sinb[t * 64 + d0];
            *(float4*)&sn[4] = *(const float4*)&sinb[t * 64 + d0 + 4];
            if (sel == 0) {
#pragma unroll
                for (int j = 0; j < 8; j++) {
                    olo[j] = __float2half_rn((lo[j] * cs[j] - hi[j] * sn[j]) * gn);
                    ohi[j] = __float2half_rn((hi[j] * cs[j] + lo[j] * sn[j]) * gn);
                }
                *(uint4*)&g_q[ob + d0]      = *(uint4*)&olo[0];
                *(uint4*)&g_q[ob + d0 + 64] = *(uint4*)&ohi[0];
            } else {
#pragma unroll
                for (int j = 0; j < 8; j++) {
                    olo[j] = __float2half_rn(lo[j] * cs[j] - hi[j] * sn[j]);
                    ohi[j] = __float2half_rn(hi[j] * cs[j] + lo[j] * sn[j]);
                }
                *(uint4*)&g_k[ob + d0]      = *(uint4*)&olo[0];
                *(uint4*)&g_k[ob + d0 + 64] = *(uint4*)&ohi[0];
            }
        }
    }
}

// ---------------- fp16 flash attention: 64x64 tiles, 128 thr, 3 CTAs/SM ------
#define QH 136    // halves per row (272B stride, conflict-free)

__global__ __launch_bounds__(128, 3) void attn_tc(__half* __restrict__ Y)
{
    extern __shared__ __half ham[];
    __half* sQ = ham;                        // [64][QH]
    __half* sK = ham + 64 * QH;              // [64][QH]
    __half* sV = ham + 128 * QH;             // [64][QH]

    const int tid  = threadIdx.x;
    const int warp = tid >> 5;               // 0..3
    const int lane = tid & 31;
    const int g    = lane >> 2;
    const int tg   = lane & 3;
    const int lm8  = lane & 7;
    const int lq   = lane >> 3;
    const int qb = (T_ / 64 - 1) - blockIdx.x;   // LPT
    const int h  = blockIdx.y;
    const int b  = blockIdx.z;
    const int q0 = qb * 64;
    const size_t bh = ((size_t)(b * H_ + h)) * T_ * D_;

    const uint32_t qAddr = smem_u32(sQ)
        + (uint32_t)((16 * warp + lm8 + ((lq & 1) << 3)) * QH) * 2
        + ((uint32_t)(lq >> 1) << 4);
    const uint32_t kAddr = smem_u32(sK)
        + (uint32_t)((lm8 + ((lq >> 1) << 3)) * QH) * 2
        + ((uint32_t)(lq & 1) << 4);
    const uint32_t vAddr = smem_u32(sV)
        + (uint32_t)((lm8 + ((lq & 1) << 3)) * QH) * 2
        + ((uint32_t)(lq >> 1) << 4);

    auto load_k = [&](int k0) {
#pragma unroll
        for (int i = 0; i < 8; i++) {
            int e = tid + i * 128;
            int row = e >> 4;
            int col = (e & 15) * 8;
            cp16(&sK[row * QH + col], g_k + bh + (size_t)(k0 + row) * D_ + col);
        }
    };
    auto load_v = [&](int k0) {
#pragma unroll
        for (int i = 0; i < 8; i++) {
            int e = tid + i * 128;
            int row = e >> 4;
            int col = (e & 15) * 8;
            cp16(&sV[row * QH + col], g_v + bh + (size_t)(k0 + row) * D_ + col);
        }
    };

    load_k(0); CP_COMMIT();
    for (int i = 0; i < 8; i++) {
        int e = tid + i * 128;
        int row = e >> 4;
        int col = (e & 15) * 8;
        *(uint4*)&sQ[row * QH + col] = *(const uint4*)(g_q + bh + (size_t)(q0 + row) * D_ + col);
    }
    __syncthreads();

    uint32_t qf[8][4];
#pragma unroll
    for (int ks = 0; ks < 8; ks++)
        LDSM_X4(qf[ks], qAddr + ks * 32);

    float yacc[16][4];
#pragma unroll
    for (int nt = 0; nt < 16; nt++)
#pragma unroll
        for (int c = 0; c < 4; c++) yacc[nt][c] = 0.f;
    float m0 = -1e30f, m1 = -1e30f, l0 = 0.f, l1 = 0.f;

    for (int kt = 0; kt <= qb; kt++) {
        const int k0 = kt * 64;

        CP_WAIT0();
        __syncthreads();

        load_v(k0); CP_COMMIT();

        float sacc[8][4];
#pragma unroll
        for (int nt = 0; nt < 8; nt++)
#pragma unroll
            for (int c = 0; c < 4; c++) sacc[nt][c] = 0.f;

#pragma unroll
        for (int ks = 0; ks < 8; ks++) {
#pragma unroll
            for (int p = 0; p < 4; p++) {
                uint32_t bqv[4];
                LDSM_X4(bqv, kAddr + (uint32_t)(p * 16 * QH * 2) + ks * 32);
                MMA_F16(sacc[2 * p],     qf[ks], bqv);
                MMA_F16(sacc[2 * p + 1], qf[ks], bqv + 2);
            }
        }

        if (kt == qb) {
            const int r0g = q0 + 16 * warp + g;
            const int r1g = r0g + 8;
#pragma unroll
            for (int nt = 0; nt < 8; nt++) {
                int c0 = k0 + nt * 8 + 2 * tg;
                if (c0     > r0g) sacc[nt][0] = -1e30f;
                if (c0 + 1 > r0g) sacc[nt][1] = -1e30f;
                if (c0     > r1g) sacc[nt][2] = -1e30f;
                if (c0 + 1 > r1g) sacc[nt][3] = -1e30f;
            }
        }

        float mx0 = -1e30f, mx1 = -1e30f;
#pragma unroll
        for (int nt = 0; nt < 8; nt++) {
            mx0 = fmaxf(mx0, fmaxf(sacc[nt][0], sacc[nt][1]));
            mx1 = fmaxf(mx1, fmaxf(sacc[nt][2], sacc[nt][3]));
        }
        mx0 = fmaxf(mx0, __shfl_xor_sync(0xffffffffu, mx0, 1));
        mx0 = fmaxf(mx0, __shfl_xor_sync(0xffffffffu, mx0, 2));
        mx1 = fmaxf(mx1, __shfl_xor_sync(0xffffffffu, mx1, 1));
        mx1 = fmaxf(mx1, __shfl_xor_sync(0xffffffffu, mx1, 2));

        float nm0 = fmaxf(m0, mx0), nm1 = fmaxf(m1, mx1);
        float cf0 = exp2x(m0 - nm0), cf1 = exp2x(m1 - nm1);
        m0 = nm0; m1 = nm1;

        float rs0 = 0.f, rs1 = 0.f;
#pragma unroll
        for (int nt = 0; nt < 8; nt++) {
            sacc[nt][0] = exp2x(sacc[nt][0] - nm0);
            sacc[nt][1] = exp2x(sacc[nt][1] - nm0);
            sacc[nt][2] = exp2x(sacc[nt][2] - nm1);
            sacc[nt][3] = exp2x(sacc[nt][3] - nm1);
            rs0 += sacc[nt][0] + sacc[nt][1];
            rs1 += sacc[nt][2] + sacc[nt][3];
        }
        rs0 += __shfl_xor_sync(0xffffffffu, rs0, 1);
        rs0 += __shfl_xor_sync(0xffffffffu, rs0, 2);
        rs1 += __shfl_xor_sync(0xffffffffu, rs1, 1);
        rs1 += __shfl_xor_sync(0xffffffffu, rs1, 2);
        l0 = l0 * cf0 + rs0;
        l1 = l1 * cf1 + rs1;

#pragma unroll
        for (int nt = 0; nt < 16; nt++) {
            yacc[nt][0] *= cf0; yacc[nt][1] *= cf0;
            yacc[nt][2] *= cf1; yacc[nt][3] *= cf1;
        }

        uint32_t pf[4][4];
#pragma unroll
        for (int ks = 0; ks < 4; ks++) {
            pf[ks][0] = packh2(sacc[2 * ks][0],     sacc[2 * ks][1]);
            pf[ks][1] = packh2(sacc[2 * ks][2],     sacc[2 * ks][3]);
            pf[ks][2] = packh2(sacc[2 * ks + 1][0], sacc[2 * ks + 1][1]);
            pf[ks][3] = packh2(sacc[2 * ks + 1][2], sacc[2 * ks + 1][3]);
        }

        CP_WAIT0();
        __syncthreads();

        if (kt < qb) { load_k(k0 + 64); CP_COMMIT(); }

#pragma unroll
        for (int ks = 0; ks < 4; ks++) {
#pragma unroll
            for (int p = 0; p < 8; p++) {
                uint32_t bqv[4];
                LDSM_X4_T(bqv, vAddr + (uint32_t)(ks * 16 * QH * 2) + p * 32);
                MMA_F16(yacc[2 * p],     pf[ks], bqv);
                MMA_F16(yacc[2 * p + 1], pf[ks], bqv + 2);
            }
        }
    }

    const float inv0 = 1.f / l0;
    const float inv1 = 1.f / l1;
    const int r0g = q0 + 16 * warp + g;
    const int r1g = r0g + 8;
#pragma unroll
    for (int nt = 0; nt < 16; nt++) {
        int col = h * D_ + nt * 8 + 2 * tg;
        *(__half2*)&Y[(size_t)(b * T_ + r0g) * C_ + col] =
            __floats2half2_rn(yacc[nt][0] * inv0, yacc[nt][1] * inv0);
        *(__half2*)&Y[(size_t)(b * T_ + r1g) * C_ + col] =
            __floats2half2_rn(yacc[nt][2] * inv1, yacc[nt][3] * inv1);
    }
}

// ---------------- launch ----------------
extern "C" void kernel_launch(void* const* d_in, const int* in_sizes, int n_in,
                              void* d_out, int out_size)
{
    const float* x     = (const float*)d_in[0];
    const float* Wqkv  = (const float*)d_in[1];
    const float* Wproj = (const float*)d_in[2];
    const float* gain  = (const float*)d_in[3];
    const float* cosb  = (const float*)d_in[4];
    const float* sinb  = (const float*)d_in[5];
    float* out = (float*)d_out;

    __half *y, *xh, *wq, *wp;
    cudaGetSymbolAddress((void**)&y,   g_y);
    cudaGetSymbolAddress((void**)&xh,  g_xh);
    cudaGetSymbolAddress((void**)&wq,  g_wq);
    cudaGetSymbolAddress((void**)&wp,  g_wp);

    const size_t gemm_smem = (size_t)4 * HS_SZ * sizeof(__half);   // 73728
    cudaFuncSetAttribute(gemm_f16, cudaFuncAttributeMaxDynamicSharedMemorySize, (int)gemm_smem);
    cudaFuncSetAttribute(gemm_qkv, cudaFuncAttributeMaxDynamicSharedMemorySize, (int)gemm_smem);

    // 0) convert inputs to fp16
    {
        int n8x = (B_ * T_ * C_) / 8;
        cvt_f16_kernel<<<(n8x + 255) / 256, 256>>>((const float4*)x, (uint4*)xh, n8x);
        int n8q = (F_ * C_) / 8;
        cvt_f16_kernel<<<(n8q + 255) / 256, 256>>>((const float4*)Wqkv, (uint4*)wq, n8q);
        int n8p = (C_ * C_) / 8;
        cvt_f16_kernel<<<(n8p + 255) / 256, 256>>>((const float4*)Wproj, (uint4*)wp, n8p);
    }

    // 1) QKV GEMM with fused RoPE/split/gain epilogue -> g_q/g_k/g_v (fp16)
    {
        dim3 grid(F_ / 128, (B_ * T_) / 128);
        gemm_qkv<<<grid, 128, gemm_smem>>>(xh, wq, gain, cosb, sinb);
    }

    // 2) attention: 64x64 tiles, 128 threads, 3 CTAs/SM
    {
        size_t smem = (size_t)3 * 64 * QH * sizeof(__half);   // 52224
        cudaFuncSetAttribute(attn_tc, cudaFuncAttributeMaxDynamicSharedMemorySize, (int)smem);
        dim3 grid(T_ / 64, H_, B_);
        attn_tc<<<grid, 128, smem>>>(y);
    }

    // 3) output projection
    {
        dim3 grid(C_ / 128, (B_ * T_) / 128);
        gemm_f16<<<grid, 128, gemm_smem>>>(y, wp, out, B_ * T_, C_, C_);
    }
}